// round 14
// baseline (speedup 1.0000x reference)
#include <cuda_runtime.h>
#include <cuda_fp16.h>
#include <cstdint>
#include <cstddef>

// Problem constants
#define T_   1024
#define B_   8
#define E_   512
#define H_   8
#define D_   64
#define BH_  (B_ * H_)          // 64
#define M_   (T_ * B_)          // 8192
#define K3E  (3 * E_)           // 1536
#define SCALE_ 0.125f

#define TT_  (T_ * T_)
#define OUT_OFF2 (2 * (size_t)T_ * B_ * E_)
#define BTT_ ((size_t)B_ * T_ * T_)

// -------------------- scratch (device globals) ------------------------------
__device__ __half g_qkv_r[(size_t)M_ * K3E];
__device__ __half g_qkv_i[(size_t)M_ * K3E];
__device__ __half g_aw_r[(size_t)BH_ * TT_];    // e = exp(logits), fp16
__device__ __half g_aw_i[(size_t)BH_ * TT_];
__device__ __half g_attn_r[(size_t)M_ * E_];
__device__ __half g_attn_i[(size_t)M_ * E_];
__device__ float g_psum[(size_t)2 * BH_ * T_ * 32];
__device__ float g_inv[(size_t)2 * BH_ * T_];
// fp16 copies of inputs
__device__ __half g_qt_r[(size_t)M_ * E_];
__device__ __half g_qt_i[(size_t)M_ * E_];
__device__ __half g_wqkv_r[(size_t)K3E * E_];
__device__ __half g_wqkv_i[(size_t)K3E * E_];
__device__ __half g_wout_r[(size_t)E_ * E_];
__device__ __half g_wout_i[(size_t)E_ * E_];

// -------------------- helpers ------------------------------------------------
__device__ __forceinline__ void mma16(float* c, const uint32_t* a, const uint32_t* b) {
    asm volatile(
        "mma.sync.aligned.m16n8k16.row.col.f32.f16.f16.f32 "
        "{%0,%1,%2,%3},{%4,%5,%6,%7},{%8,%9},{%0,%1,%2,%3};"
        : "+f"(c[0]), "+f"(c[1]), "+f"(c[2]), "+f"(c[3])
        : "r"(a[0]), "r"(a[1]), "r"(a[2]), "r"(a[3]), "r"(b[0]), "r"(b[1]));
}

__device__ __forceinline__ void ldsm4(uint32_t* r, uint32_t addr) {
    asm volatile(
        "ldmatrix.sync.aligned.m8n8.x4.shared.b16 {%0,%1,%2,%3}, [%4];"
        : "=r"(r[0]), "=r"(r[1]), "=r"(r[2]), "=r"(r[3]) : "r"(addr));
}
__device__ __forceinline__ void ldsm4t(uint32_t* r, uint32_t addr) {
    asm volatile(
        "ldmatrix.sync.aligned.m8n8.x4.trans.shared.b16 {%0,%1,%2,%3}, [%4];"
        : "=r"(r[0]), "=r"(r[1]), "=r"(r[2]), "=r"(r[3]) : "r"(addr));
}

__device__ __forceinline__ void cp16(uint32_t s, const void* g) {
    asm volatile("cp.async.cg.shared.global [%0], [%1], 16;"
                 :: "r"(s), "l"((unsigned long long)__cvta_generic_to_global(g)));
}

__device__ __forceinline__ uint32_t smem_u32(const void* p) {
    return (uint32_t)__cvta_generic_to_shared(p);
}

// ---------------------------------------------------------------------------
// Merged conversion pass: fp32 -> fp16 for all six input tensors.
// ---------------------------------------------------------------------------
#define N4_Q  (M_ * E_ / 4)
#define N4_WQ (K3E * E_ / 4)
#define N4_WO (E_ * E_ / 4)
#define N4_TOTAL (2 * (N4_Q + N4_WQ + N4_WO))

__global__ __launch_bounds__(256) void cvt_all_kernel(
    const float* __restrict__ s0, const float* __restrict__ s1,
    const float* __restrict__ s2, const float* __restrict__ s3,
    const float* __restrict__ s4, const float* __restrict__ s5,
    __half* __restrict__ d0, __half* __restrict__ d1,
    __half* __restrict__ d2, __half* __restrict__ d3,
    __half* __restrict__ d4, __half* __restrict__ d5)
{
    int i = blockIdx.x * 256 + threadIdx.x;
    if (i >= N4_TOTAL) return;
    const float* src;
    __half* dst;
    int j = i;
    if (j < N4_Q)                  { src = s0; dst = d0; }
    else if ((j -= N4_Q) < N4_Q)   { src = s1; dst = d1; }
    else if ((j -= N4_Q) < N4_WQ)  { src = s2; dst = d2; }
    else if ((j -= N4_WQ) < N4_WQ) { src = s3; dst = d3; }
    else if ((j -= N4_WQ) < N4_WO) { src = s4; dst = d4; }
    else { j -= N4_WO;               src = s5; dst = d5; }
    float4 v = ((const float4*)src)[j];
    __half2 h0 = __floats2half2_rn(v.x, v.y);
    __half2 h1 = __floats2half2_rn(v.z, v.w);
    ((__half2*)(dst + (size_t)j * 4))[0] = h0;
    ((__half2*)(dst + (size_t)j * 4))[1] = h1;
}

// ---------------------------------------------------------------------------
// Complex GEMM on fp16 tensor cores (m16n8k16, fp32 accumulate).
// ---------------------------------------------------------------------------
template <bool CONJ, bool EXP_C, bool OUT_HALF>
__global__ __launch_bounds__(256, 2)
void cmma_kernel(const __half* __restrict__ Ar, const __half* __restrict__ Ai,
                 long lda, long sA1, long sA2,
                 const __half* __restrict__ Br, const __half* __restrict__ Bi,
                 long ldb, long sB1, long sB2,
                 void* __restrict__ Crv, void* __restrict__ Civ,
                 long ldc, long sC1, long sC2,
                 const float* __restrict__ biasr, const float* __restrict__ biasi,
                 float* __restrict__ psum,
                 float alpha, int K)
{
    extern __shared__ __half smh[];
    constexpr int ASH = 128 * 72;
    constexpr int BSH = 64 * 72;
    __half* AsR = smh;
    __half* AsI = smh + 2 * ASH;
    __half* BsR = smh + 4 * ASH;
    __half* BsI = smh + 4 * ASH + 2 * BSH;

    const int tid  = threadIdx.x;
    const int lane = tid & 31;
    const int warp = tid >> 5;
    const int wm   = warp & 3;
    const int wn   = warp >> 2;
    const int grp  = lane >> 2;
    const int quad = lane & 3;
    const int subm = lane >> 3;
    const int rin  = lane & 7;

    const int bz = blockIdx.z;
    const int zb = bz >> 3, zh = bz & 7;
    const int m0 = blockIdx.y << 7;
    const int n0 = blockIdx.x << 6;

    const __half* ArB = Ar + (size_t)zb * sA1 + (size_t)zh * sA2;
    const __half* AiB = Ai + (size_t)zb * sA1 + (size_t)zh * sA2;
    const __half* BrB = Br + (size_t)zb * sB1 + (size_t)zh * sB2;
    const __half* BiB = Bi + (size_t)zb * sB1 + (size_t)zh * sB2;

    const uint32_t sAsR = smem_u32(AsR);
    const uint32_t sAsI = smem_u32(AsI);
    const uint32_t sBsR = smem_u32(BsR);
    const uint32_t sBsI = smem_u32(BsI);

    const uint32_t aoff = (uint32_t)((wm * 32 + (subm & 1) * 8 + rin) * 144 +
                                     (subm >> 1) * 16);
    const uint32_t aR0 = sAsR + aoff;
    const uint32_t aI0 = sAsI + aoff;
    const uint32_t boff = (uint32_t)((wn * 32 + rin) * 144 + (subm & 1) * 16);
    const uint32_t bB0 = ((subm >> 1) ? sBsI : sBsR) + boff;

    float cr[2][4][4], ci[2][4][4];
#pragma unroll
    for (int mi = 0; mi < 2; mi++)
#pragma unroll
        for (int ni = 0; ni < 4; ni++)
#pragma unroll
            for (int r = 0; r < 4; r++) { cr[mi][ni][r] = 0.f; ci[mi][ni][r] = 0.f; }

    const int NC = K >> 6;

    auto load_chunk = [&](int c, int buf) {
        const int k0 = c << 6;
#pragma unroll
        for (int j = 0; j < 4; j++) {
            int idx = tid + j * 256;
            int row = idx >> 3;
            int c8  = (idx & 7) << 3;
            uint32_t so = (uint32_t)(buf * ASH * 2 + row * 144 + c8 * 2);
            cp16(sAsR + so, ArB + (size_t)(m0 + row) * lda + k0 + c8);
            cp16(sAsI + so, AiB + (size_t)(m0 + row) * lda + k0 + c8);
        }
#pragma unroll
        for (int j = 0; j < 2; j++) {
            int idx = tid + j * 256;
            int row = idx >> 3;
            int c8  = (idx & 7) << 3;
            uint32_t so = (uint32_t)(buf * BSH * 2 + row * 144 + c8 * 2);
            cp16(sBsR + so, BrB + (size_t)(n0 + row) * ldb + k0 + c8);
            cp16(sBsI + so, BiB + (size_t)(n0 + row) * ldb + k0 + c8);
        }
    };

    load_chunk(0, 0);
    asm volatile("cp.async.commit_group;");

    for (int c = 0; c < NC; c++) {
        if (c + 1 < NC) load_chunk(c + 1, (c + 1) & 1);
        asm volatile("cp.async.commit_group;");
        asm volatile("cp.async.wait_group 1;");
        __syncthreads();

        const uint32_t bufA = (uint32_t)((c & 1) * ASH * 2);
        const uint32_t bufB = (uint32_t)((c & 1) * BSH * 2);

#pragma unroll
        for (int ks = 0; ks < 4; ks++) {
            const uint32_t kso = (uint32_t)(ks * 32);
            uint32_t afr[2][4], afi[2][4];
            ldsm4(afr[0], aR0 + bufA + kso);
            ldsm4(afr[1], aR0 + bufA + kso + 2304);
            ldsm4(afi[0], aI0 + bufA + kso);
            ldsm4(afi[1], aI0 + bufA + kso + 2304);
#pragma unroll
            for (int ni = 0; ni < 4; ni++) {
                uint32_t bt[4], bfx[2];
                ldsm4(bt, bB0 + bufB + kso + (uint32_t)(ni * 1152));
                bfx[0] = bt[2] ^ 0x80008000u;
                bfx[1] = bt[3] ^ 0x80008000u;
#pragma unroll
                for (int mi = 0; mi < 2; mi++) {
                    mma16(cr[mi][ni], afr[mi], bt);
                    mma16(cr[mi][ni], afi[mi], CONJ ? (bt + 2) : bfx);
                    mma16(ci[mi][ni], afi[mi], bt);
                    mma16(ci[mi][ni], afr[mi], CONJ ? bfx : (bt + 2));
                }
            }
        }
        __syncthreads();
    }

    if (EXP_C) {
#pragma unroll
        for (int mi = 0; mi < 2; mi++)
#pragma unroll
            for (int ni = 0; ni < 4; ni++)
#pragma unroll
                for (int r = 0; r < 4; r++) {
                    cr[mi][ni][r] = __expf(cr[mi][ni][r] * alpha);
                    ci[mi][ni][r] = __expf(ci[mi][ni][r] * alpha);
                }
#pragma unroll
        for (int comp = 0; comp < 2; comp++) {
            float (*acc)[4][4] = comp ? ci : cr;
#pragma unroll
            for (int mi = 0; mi < 2; mi++) {
                float s0 = 0.f, s1 = 0.f;
#pragma unroll
                for (int ni = 0; ni < 4; ni++) {
                    s0 += acc[mi][ni][0] + acc[mi][ni][1];
                    s1 += acc[mi][ni][2] + acc[mi][ni][3];
                }
                s0 += __shfl_xor_sync(0xffffffffu, s0, 1);
                s0 += __shfl_xor_sync(0xffffffffu, s0, 2);
                s1 += __shfl_xor_sync(0xffffffffu, s1, 1);
                s1 += __shfl_xor_sync(0xffffffffu, s1, 2);
                if (quad == 0) {
                    int row = m0 + wm * 32 + mi * 16 + grp;
                    size_t base = ((size_t)(comp * BH_ + bz) * T_);
                    int slot = blockIdx.x * 2 + wn;
                    psum[(base + row) * 32 + slot] = s0;
                    psum[(base + row + 8) * 32 + slot] = s1;
                }
            }
        }
    }

    // Epilogue
#pragma unroll
    for (int mi = 0; mi < 2; mi++) {
#pragma unroll
        for (int ni = 0; ni < 4; ni++) {
            int m = m0 + wm * 32 + mi * 16 + grp;
            int n = n0 + wn * 32 + ni * 8 + quad * 2;
            float vr0, vr1, vr2, vr3, vi0, vi1, vi2, vi3;
            if (EXP_C) {
                vr0 = cr[mi][ni][0]; vr1 = cr[mi][ni][1];
                vr2 = cr[mi][ni][2]; vr3 = cr[mi][ni][3];
                vi0 = ci[mi][ni][0]; vi1 = ci[mi][ni][1];
                vi2 = ci[mi][ni][2]; vi3 = ci[mi][ni][3];
            } else {
                float br0 = 0.f, br1 = 0.f, bi0 = 0.f, bi1 = 0.f;
                if (biasr) {
                    br0 = biasr[n]; br1 = biasr[n + 1];
                    bi0 = biasi[n]; bi1 = biasi[n + 1];
                }
                vr0 = cr[mi][ni][0] * alpha + br0;
                vr1 = cr[mi][ni][1] * alpha + br1;
                vr2 = cr[mi][ni][2] * alpha + br0;
                vr3 = cr[mi][ni][3] * alpha + br1;
                vi0 = ci[mi][ni][0] * alpha + bi0;
                vi1 = ci[mi][ni][1] * alpha + bi1;
                vi2 = ci[mi][ni][2] * alpha + bi0;
                vi3 = ci[mi][ni][3] * alpha + bi1;
            }
            if (OUT_HALF) {
                __half* CrB = (__half*)Crv + (size_t)zb * sC1 + (size_t)zh * sC2;
                __half* CiB = (__half*)Civ + (size_t)zb * sC1 + (size_t)zh * sC2;
                *(__half2*)(CrB + (size_t)m * ldc + n) = __floats2half2_rn(vr0, vr1);
                *(__half2*)(CrB + (size_t)(m + 8) * ldc + n) = __floats2half2_rn(vr2, vr3);
                *(__half2*)(CiB + (size_t)m * ldc + n) = __floats2half2_rn(vi0, vi1);
                *(__half2*)(CiB + (size_t)(m + 8) * ldc + n) = __floats2half2_rn(vi2, vi3);
            } else {
                float* CrB = (float*)Crv + (size_t)zb * sC1 + (size_t)zh * sC2;
                float* CiB = (float*)Civ + (size_t)zb * sC1 + (size_t)zh * sC2;
                float2 v;
                v.x = vr0; v.y = vr1;
                *(float2*)(CrB + (size_t)m * ldc + n) = v;
                v.x = vr2; v.y = vr3;
                *(float2*)(CrB + (size_t)(m + 8) * ldc + n) = v;
                v.x = vi0; v.y = vi1;
                *(float2*)(CiB + (size_t)m * ldc + n) = v;
                v.x = vi2; v.y = vi3;
                *(float2*)(CiB + (size_t)(m + 8) * ldc + n) = v;
            }
        }
    }
}

// ---------------------------------------------------------------------------
// inv kernel: g_inv[row] = 1 / sum(g_psum[row][0..31])  (for PV)
// ---------------------------------------------------------------------------
__global__ __launch_bounds__(256) void inv_kernel()
{
    int row = blockIdx.x * 256 + threadIdx.x;
    if (row >= 2 * BH_ * T_) return;
    const float4* p = (const float4*)(g_psum + (size_t)row * 32);
    float s = 0.f;
#pragma unroll
    for (int j = 0; j < 8; j++) {
        float4 v = p[j];
        s += (v.x + v.y) + (v.z + v.w);
    }
    g_inv[row] = 1.0f / s;
}

// ---------------------------------------------------------------------------
// avg kernel (side stream): computes its own inv8 from psum (bit-identical
// order to inv_kernel), batches all 8 head loads for MLP, streams the
// head-average. Depends ONLY on g_aw/g_psum — independent of PV.
// ---------------------------------------------------------------------------
__global__ __launch_bounds__(256) void avg_kernel(float* __restrict__ out)
{
    const int t = blockIdx.x;
    const int b = blockIdx.y;
    const int comp = blockIdx.z;
    const __half* buf = comp ? g_aw_i : g_aw_r;

    const int tid = threadIdx.x;
    __shared__ float inv8[H_];
    if (tid < H_) {
        size_t row = ((size_t)comp * BH_ + b * H_ + tid) * T_ + t;
        const float4* p = (const float4*)(g_psum + row * 32);
        float s = 0.f;
#pragma unroll
        for (int j = 0; j < 8; j++) {
            float4 v = p[j];
            s += (v.x + v.y) + (v.z + v.w);
        }
        inv8[tid] = 1.0f / s;
    }

    // batch all head loads (8x MLP) before the barrier
    __half2 e[H_][2];
#pragma unroll
    for (int h = 0; h < H_; h++) {
        const __half2* p = (const __half2*)(buf +
            ((size_t)(b * H_ + h) * T_ + t) * T_ + (tid << 2));
        e[h][0] = p[0];
        e[h][1] = p[1];
    }
    __syncthreads();

    float4 acc = {0.f, 0.f, 0.f, 0.f};
#pragma unroll
    for (int h = 0; h < H_; h++) {
        float2 e0 = __half22float2(e[h][0]);
        float2 e1 = __half22float2(e[h][1]);
        const float iv = inv8[h];
        acc.x += e0.x * iv; acc.y += e0.y * iv;
        acc.z += e1.x * iv; acc.w += e1.y * iv;
    }
    const float inv8f = 1.0f / (float)H_;
    acc.x *= inv8f; acc.y *= inv8f; acc.z *= inv8f; acc.w *= inv8f;
    size_t o = OUT_OFF2 + (size_t)comp * BTT_ + ((size_t)b * T_ + t) * T_ + (tid << 2);
    *(float4*)&out[o] = acc;
}

// ---------------------------------------------------------------------------
// PV fp16: 4 accumulator groups, normalize in epilogue, 3-stage pipeline.
// ---------------------------------------------------------------------------
__global__ __launch_bounds__(256, 2)
void pv_kernel()
{
    extern __shared__ __half smh[];
    constexpr int ASH = 64 * 72;
    constexpr int BSH = 64 * 72;
    __half* AsR = smh;
    __half* AsI = smh + 3 * ASH;
    __half* BsR = smh + 6 * ASH;
    __half* BsI = smh + 6 * ASH + 3 * BSH;

    const int tid  = threadIdx.x;
    const int lane = tid & 31;
    const int warp = tid >> 5;
    const int wm   = warp & 3;
    const int wn   = warp >> 2;
    const int grp  = lane >> 2;
    const int quad = lane & 3;
    const int subm = lane >> 3;
    const int rin  = lane & 7;

    const int bh = blockIdx.y;
    const int b = bh >> 3, h = bh & 7;
    const int m0 = blockIdx.x << 6;

    const __half* ArB = g_aw_r + (size_t)bh * TT_;
    const __half* AiB = g_aw_i + (size_t)bh * TT_;

    const uint32_t sAsR = smem_u32(AsR);
    const uint32_t sAsI = smem_u32(AsI);
    const uint32_t sBsR = smem_u32(BsR);
    const uint32_t sBsI = smem_u32(BsI);

    const uint32_t aoff = (uint32_t)((wm * 16 + (subm & 1) * 8 + rin) * 144 +
                                     (subm >> 1) * 16);
    const uint32_t aR0 = sAsR + aoff;
    const uint32_t aI0 = sAsI + aoff;
    const uint32_t voff = (uint32_t)(((subm & 1) * 8 + rin) * 144 + wn * 64);
    const uint32_t vB0 = ((subm >> 1) ? sBsI : sBsR) + voff;

    float X[4][4], Y[4][4], Z[4][4], W[4][4];
#pragma unroll
    for (int ni = 0; ni < 4; ni++)
#pragma unroll
        for (int r = 0; r < 4; r++) {
            X[ni][r] = 0.f; Y[ni][r] = 0.f; Z[ni][r] = 0.f; W[ni][r] = 0.f;
        }

    auto load_chunk = [&](int c, int buf) {
        const int k0 = c << 6;
#pragma unroll
        for (int j = 0; j < 2; j++) {
            int idx = tid + j * 256;
            int row = idx >> 3;
            int c8  = (idx & 7) << 3;
            uint32_t so = (uint32_t)(buf * ASH * 2 + row * 144 + c8 * 2);
            cp16(sAsR + so, ArB + (size_t)(m0 + row) * T_ + k0 + c8);
            cp16(sAsI + so, AiB + (size_t)(m0 + row) * T_ + k0 + c8);
        }
#pragma unroll
        for (int j = 0; j < 2; j++) {
            int idx = tid + j * 256;
            int row = idx >> 3;
            int c8  = (idx & 7) << 3;
            uint32_t so = (uint32_t)(buf * BSH * 2 + row * 144 + c8 * 2);
            size_t voffg = ((size_t)(k0 + row) * B_ + b) * K3E + 2 * E_ + h * D_ + c8;
            cp16(sBsR + so, g_qkv_r + voffg);
            cp16(sBsI + so, g_qkv_i + voffg);
        }
        asm volatile("cp.async.commit_group;");
    };

    const int NC = T_ >> 6;
    load_chunk(0, 0);
    load_chunk(1, 1);

    int sc = 0, sp = 2;
    for (int c = 0; c < NC; c++) {
        if (c + 1 < NC) asm volatile("cp.async.wait_group 1;");
        else            asm volatile("cp.async.wait_group 0;");
        __syncthreads();
        if (c + 2 < NC) {
            load_chunk(c + 2, sp);
            sp = (sp == 2) ? 0 : sp + 1;
        }

        const uint32_t bufA = (uint32_t)(sc * ASH * 2);
        const uint32_t bufB = (uint32_t)(sc * BSH * 2);
        sc = (sc == 2) ? 0 : sc + 1;

#pragma unroll
        for (int ks = 0; ks < 4; ks++) {
            const uint32_t kso = (uint32_t)(ks * 32);
            uint32_t aer[4], aei[4];
            ldsm4(aer, aR0 + bufA + kso);
            ldsm4(aei, aI0 + bufA + kso);
#pragma unroll
            for (int ni = 0; ni < 4; ni++) {
                uint32_t bt[4];
                ldsm4t(bt, vB0 + bufB + (uint32_t)(ks * 16 * 144) + (uint32_t)(ni * 16));
                mma16(X[ni], aer, bt);
                mma16(Y[ni], aei, bt + 2);
                mma16(Z[ni], aei, bt);
                mma16(W[ni], aer, bt + 2);
            }
        }
    }

    const int m  = m0 + wm * 16 + grp;
    const float ir0 = g_inv[(size_t)bh * T_ + m];
    const float ir1 = g_inv[(size_t)bh * T_ + m + 8];
    const float ii0 = g_inv[((size_t)BH_ + bh) * T_ + m];
    const float ii1 = g_inv[((size_t)BH_ + bh) * T_ + m + 8];
#pragma unroll
    for (int ni = 0; ni < 4; ni++) {
        int n = wn * 32 + ni * 8 + quad * 2;
        size_t o0 = ((size_t)m * B_ + b) * E_ + h * D_ + n;
        size_t o1 = ((size_t)(m + 8) * B_ + b) * E_ + h * D_ + n;
        *(__half2*)(g_attn_r + o0) = __floats2half2_rn(
            ir0 * X[ni][0] + ii0 * Y[ni][0], ir0 * X[ni][1] + ii0 * Y[ni][1]);
        *(__half2*)(g_attn_r + o1) = __floats2half2_rn(
            ir1 * X[ni][2] + ii1 * Y[ni][2], ir1 * X[ni][3] + ii1 * Y[ni][3]);
        *(__half2*)(g_attn_i + o0) = __floats2half2_rn(
            ii0 * Z[ni][0] - ir0 * W[ni][0], ii0 * Z[ni][1] - ir0 * W[ni][1]);
        *(__half2*)(g_attn_i + o1) = __floats2half2_rn(
            ii1 * Z[ni][2] - ir1 * W[ni][2], ii1 * Z[ni][3] - ir1 * W[ni][3]);
    }
}

// ---------------------------------------------------------------------------
extern "C" void kernel_launch(void* const* d_in, const int* in_sizes, int n_in,
                              void* d_out, int out_size)
{
    const float* query_r = (const float*)d_in[0];
    const float* query_i = (const float*)d_in[1];
    const float* W_qkv_r = (const float*)d_in[2];
    const float* W_qkv_i = (const float*)d_in[3];
    const float* b_qkv_r = (const float*)d_in[4];
    const float* b_qkv_i = (const float*)d_in[5];
    const float* W_out_r = (const float*)d_in[6];
    const float* W_out_i = (const float*)d_in[7];
    const float* b_out_r = (const float*)d_in[8];
    const float* b_out_i = (const float*)d_in[9];
    float* out = (float*)d_out;

    __half *gqkvr, *gqkvi, *gawr, *gawi, *gatr, *gati;
    __half *gqtr, *gqti, *gwqr, *gwqi, *gwor, *gwoi;
    float *gpsum;
    cudaGetSymbolAddress((void**)&gqkvr, g_qkv_r);
    cudaGetSymbolAddress((void**)&gqkvi, g_qkv_i);
    cudaGetSymbolAddress((void**)&gawr, g_aw_r);
    cudaGetSymbolAddress((void**)&gawi, g_aw_i);
    cudaGetSymbolAddress((void**)&gatr, g_attn_r);
    cudaGetSymbolAddress((void**)&gati, g_attn_i);
    cudaGetSymbolAddress((void**)&gpsum, g_psum);
    cudaGetSymbolAddress((void**)&gqtr, g_qt_r);
    cudaGetSymbolAddress((void**)&gqti, g_qt_i);
    cudaGetSymbolAddress((void**)&gwqr, g_wqkv_r);
    cudaGetSymbolAddress((void**)&gwqi, g_wqkv_i);
    cudaGetSymbolAddress((void**)&gwor, g_wout_r);
    cudaGetSymbolAddress((void**)&gwoi, g_wout_i);

    // Lazily-created side stream + events for avg/PV overlap (host-side
    // resources only; no device memory allocation).
    static cudaStream_t s2 = nullptr;
    static cudaEvent_t evFork = nullptr, evJoin = nullptr;
    if (s2 == nullptr) {
        cudaStreamCreateWithFlags(&s2, cudaStreamNonBlocking);
        cudaEventCreateWithFlags(&evFork, cudaEventDisableTiming);
        cudaEventCreateWithFlags(&evJoin, cudaEventDisableTiming);
    }

    const int SMEM_NK = (4 * 128 * 72 + 4 * 64 * 72) * 2;   // 110592 B
    const int SMEM_PV = (6 * 64 * 72 + 6 * 64 * 72) * 2;    // 110592 B

    cudaFuncSetAttribute((const void*)cmma_kernel<false, false, true>,
                         cudaFuncAttributeMaxDynamicSharedMemorySize, SMEM_NK);
    cudaFuncSetAttribute((const void*)cmma_kernel<true, true, true>,
                         cudaFuncAttributeMaxDynamicSharedMemorySize, SMEM_NK);
    cudaFuncSetAttribute((const void*)cmma_kernel<false, false, false>,
                         cudaFuncAttributeMaxDynamicSharedMemorySize, SMEM_NK);
    cudaFuncSetAttribute((const void*)pv_kernel,
                         cudaFuncAttributeMaxDynamicSharedMemorySize, SMEM_PV);

    dim3 blk(256);

    // 0) Convert all GEMM inputs to fp16
    cvt_all_kernel<<<(N4_TOTAL + 255) / 256, blk>>>(
        query_r, query_i, W_qkv_r, W_qkv_i, W_out_r, W_out_i,
        gqtr, gqti, gwqr, gwqi, gwor, gwoi);

    // 1) QKV complex linear (half outputs)
    cmma_kernel<false, false, true>
        <<<dim3(K3E / 64, M_ / 128, 1), blk, SMEM_NK>>>(
        gqtr, gqti, E_, 0, 0,
        gwqr, gwqi, E_, 0, 0,
        gqkvr, gqkvi, K3E, 0, 0,
        b_qkv_r, b_qkv_i, nullptr, 1.0f, E_);

    // 2) Scores -> e = exp(SCALE*logits) (half) + per-row psum
    cmma_kernel<true, true, true>
        <<<dim3(T_ / 64, T_ / 128, BH_), blk, SMEM_NK>>>(
        gqkvr, gqkvi, (long)B_ * K3E, K3E, D_,
        gqkvr + E_, gqkvi + E_, (long)B_ * K3E, K3E, D_,
        gawr, gawi, T_, (long)8 * TT_, (long)TT_,
        nullptr, nullptr, gpsum, SCALE_, D_);

    // 3) Row-sum inverses (for PV)
    inv_kernel<<<dim3(2 * BH_ * T_ / 256), blk>>>();

    // ---- fork: avg (DRAM-bound) runs on s2, concurrent with PV + out ----
    cudaEventRecord(evFork, 0);
    cudaStreamWaitEvent(s2, evFork, 0);
    avg_kernel<<<dim3(T_, B_, 2), blk, 0, s2>>>(out);
    cudaEventRecord(evJoin, s2);

    // 4) PV with in-epilogue normalization (main stream)
    pv_kernel<<<dim3(T_ / 64, BH_), blk, SMEM_PV>>>();

    // 5) Output complex linear -> d_out head (float)
    cmma_kernel<false, false, false>
        <<<dim3(E_ / 64, M_ / 128, 1), blk, SMEM_NK>>>(
        gatr, gati, E_, 0, 0,
        gwor, gwoi, E_, 0, 0,
        out, out + (size_t)M_ * E_, E_, 0, 0,
        b_out_r, b_out_i, nullptr, 1.0f, E_);

    // ---- join: main stream completes only after avg ----
    cudaStreamWaitEvent(0, evJoin, 0);
}

// round 15
// speedup vs baseline: 1.0110x; 1.0110x over previous
#include <cuda_runtime.h>
#include <cuda_fp16.h>
#include <cstdint>
#include <cstddef>

// Problem constants
#define T_   1024
#define B_   8
#define E_   512
#define H_   8
#define D_   64
#define BH_  (B_ * H_)          // 64
#define M_   (T_ * B_)          // 8192
#define K3E  (3 * E_)           // 1536
#define SCALE_ 0.125f

#define TT_  (T_ * T_)
#define OUT_OFF2 (2 * (size_t)T_ * B_ * E_)
#define BTT_ ((size_t)B_ * T_ * T_)

// -------------------- scratch (device globals) ------------------------------
__device__ __half g_qkv_r[(size_t)M_ * K3E];
__device__ __half g_qkv_i[(size_t)M_ * K3E];
__device__ __half g_aw_r[(size_t)BH_ * TT_];    // e = exp(logits), fp16
__device__ __half g_aw_i[(size_t)BH_ * TT_];
__device__ __half g_attn_r[(size_t)M_ * E_];
__device__ __half g_attn_i[(size_t)M_ * E_];
__device__ float g_psum[(size_t)2 * BH_ * T_ * 32];
// fp16 copies of inputs
__device__ __half g_qt_r[(size_t)M_ * E_];
__device__ __half g_qt_i[(size_t)M_ * E_];
__device__ __half g_wqkv_r[(size_t)K3E * E_];
__device__ __half g_wqkv_i[(size_t)K3E * E_];
__device__ __half g_wout_r[(size_t)E_ * E_];
__device__ __half g_wout_i[(size_t)E_ * E_];

// -------------------- helpers ------------------------------------------------
__device__ __forceinline__ void mma16(float* c, const uint32_t* a, const uint32_t* b) {
    asm volatile(
        "mma.sync.aligned.m16n8k16.row.col.f32.f16.f16.f32 "
        "{%0,%1,%2,%3},{%4,%5,%6,%7},{%8,%9},{%0,%1,%2,%3};"
        : "+f"(c[0]), "+f"(c[1]), "+f"(c[2]), "+f"(c[3])
        : "r"(a[0]), "r"(a[1]), "r"(a[2]), "r"(a[3]), "r"(b[0]), "r"(b[1]));
}

__device__ __forceinline__ void ldsm4(uint32_t* r, uint32_t addr) {
    asm volatile(
        "ldmatrix.sync.aligned.m8n8.x4.shared.b16 {%0,%1,%2,%3}, [%4];"
        : "=r"(r[0]), "=r"(r[1]), "=r"(r[2]), "=r"(r[3]) : "r"(addr));
}
__device__ __forceinline__ void ldsm4t(uint32_t* r, uint32_t addr) {
    asm volatile(
        "ldmatrix.sync.aligned.m8n8.x4.trans.shared.b16 {%0,%1,%2,%3}, [%4];"
        : "=r"(r[0]), "=r"(r[1]), "=r"(r[2]), "=r"(r[3]) : "r"(addr));
}

__device__ __forceinline__ void cp16(uint32_t s, const void* g) {
    asm volatile("cp.async.cg.shared.global [%0], [%1], 16;"
                 :: "r"(s), "l"((unsigned long long)__cvta_generic_to_global(g)));
}

__device__ __forceinline__ uint32_t smem_u32(const void* p) {
    return (uint32_t)__cvta_generic_to_shared(p);
}

// ---------------------------------------------------------------------------
// Merged conversion pass: fp32 -> fp16 for all six input tensors.
// ---------------------------------------------------------------------------
#define N4_Q  (M_ * E_ / 4)
#define N4_WQ (K3E * E_ / 4)
#define N4_WO (E_ * E_ / 4)
#define N4_TOTAL (2 * (N4_Q + N4_WQ + N4_WO))

__global__ __launch_bounds__(256) void cvt_all_kernel(
    const float* __restrict__ s0, const float* __restrict__ s1,
    const float* __restrict__ s2, const float* __restrict__ s3,
    const float* __restrict__ s4, const float* __restrict__ s5,
    __half* __restrict__ d0, __half* __restrict__ d1,
    __half* __restrict__ d2, __half* __restrict__ d3,
    __half* __restrict__ d4, __half* __restrict__ d5)
{
    int i = blockIdx.x * 256 + threadIdx.x;
    if (i >= N4_TOTAL) return;
    const float* src;
    __half* dst;
    int j = i;
    if (j < N4_Q)                  { src = s0; dst = d0; }
    else if ((j -= N4_Q) < N4_Q)   { src = s1; dst = d1; }
    else if ((j -= N4_Q) < N4_WQ)  { src = s2; dst = d2; }
    else if ((j -= N4_WQ) < N4_WQ) { src = s3; dst = d3; }
    else if ((j -= N4_WQ) < N4_WO) { src = s4; dst = d4; }
    else { j -= N4_WO;               src = s5; dst = d5; }
    float4 v = ((const float4*)src)[j];
    __half2 h0 = __floats2half2_rn(v.x, v.y);
    __half2 h1 = __floats2half2_rn(v.z, v.w);
    ((__half2*)(dst + (size_t)j * 4))[0] = h0;
    ((__half2*)(dst + (size_t)j * 4))[1] = h1;
}

// ---------------------------------------------------------------------------
// Complex GEMM on fp16 tensor cores (m16n8k16, fp32 accumulate).
// ---------------------------------------------------------------------------
template <bool CONJ, bool EXP_C, bool OUT_HALF>
__global__ __launch_bounds__(256, 2)
void cmma_kernel(const __half* __restrict__ Ar, const __half* __restrict__ Ai,
                 long lda, long sA1, long sA2,
                 const __half* __restrict__ Br, const __half* __restrict__ Bi,
                 long ldb, long sB1, long sB2,
                 void* __restrict__ Crv, void* __restrict__ Civ,
                 long ldc, long sC1, long sC2,
                 const float* __restrict__ biasr, const float* __restrict__ biasi,
                 float* __restrict__ psum,
                 float alpha, int K)
{
    extern __shared__ __half smh[];
    constexpr int ASH = 128 * 72;
    constexpr int BSH = 64 * 72;
    __half* AsR = smh;
    __half* AsI = smh + 2 * ASH;
    __half* BsR = smh + 4 * ASH;
    __half* BsI = smh + 4 * ASH + 2 * BSH;

    const int tid  = threadIdx.x;
    const int lane = tid & 31;
    const int warp = tid >> 5;
    const int wm   = warp & 3;
    const int wn   = warp >> 2;
    const int grp  = lane >> 2;
    const int quad = lane & 3;
    const int subm = lane >> 3;
    const int rin  = lane & 7;

    const int bz = blockIdx.z;
    const int zb = bz >> 3, zh = bz & 7;
    const int m0 = blockIdx.y << 7;
    const int n0 = blockIdx.x << 6;

    const __half* ArB = Ar + (size_t)zb * sA1 + (size_t)zh * sA2;
    const __half* AiB = Ai + (size_t)zb * sA1 + (size_t)zh * sA2;
    const __half* BrB = Br + (size_t)zb * sB1 + (size_t)zh * sB2;
    const __half* BiB = Bi + (size_t)zb * sB1 + (size_t)zh * sB2;

    const uint32_t sAsR = smem_u32(AsR);
    const uint32_t sAsI = smem_u32(AsI);
    const uint32_t sBsR = smem_u32(BsR);
    const uint32_t sBsI = smem_u32(BsI);

    const uint32_t aoff = (uint32_t)((wm * 32 + (subm & 1) * 8 + rin) * 144 +
                                     (subm >> 1) * 16);
    const uint32_t aR0 = sAsR + aoff;
    const uint32_t aI0 = sAsI + aoff;
    const uint32_t boff = (uint32_t)((wn * 32 + rin) * 144 + (subm & 1) * 16);
    const uint32_t bB0 = ((subm >> 1) ? sBsI : sBsR) + boff;

    float cr[2][4][4], ci[2][4][4];
#pragma unroll
    for (int mi = 0; mi < 2; mi++)
#pragma unroll
        for (int ni = 0; ni < 4; ni++)
#pragma unroll
            for (int r = 0; r < 4; r++) { cr[mi][ni][r] = 0.f; ci[mi][ni][r] = 0.f; }

    const int NC = K >> 6;

    auto load_chunk = [&](int c, int buf) {
        const int k0 = c << 6;
#pragma unroll
        for (int j = 0; j < 4; j++) {
            int idx = tid + j * 256;
            int row = idx >> 3;
            int c8  = (idx & 7) << 3;
            uint32_t so = (uint32_t)(buf * ASH * 2 + row * 144 + c8 * 2);
            cp16(sAsR + so, ArB + (size_t)(m0 + row) * lda + k0 + c8);
            cp16(sAsI + so, AiB + (size_t)(m0 + row) * lda + k0 + c8);
        }
#pragma unroll
        for (int j = 0; j < 2; j++) {
            int idx = tid + j * 256;
            int row = idx >> 3;
            int c8  = (idx & 7) << 3;
            uint32_t so = (uint32_t)(buf * BSH * 2 + row * 144 + c8 * 2);
            cp16(sBsR + so, BrB + (size_t)(n0 + row) * ldb + k0 + c8);
            cp16(sBsI + so, BiB + (size_t)(n0 + row) * ldb + k0 + c8);
        }
    };

    load_chunk(0, 0);
    asm volatile("cp.async.commit_group;");

    for (int c = 0; c < NC; c++) {
        if (c + 1 < NC) load_chunk(c + 1, (c + 1) & 1);
        asm volatile("cp.async.commit_group;");
        asm volatile("cp.async.wait_group 1;");
        __syncthreads();

        const uint32_t bufA = (uint32_t)((c & 1) * ASH * 2);
        const uint32_t bufB = (uint32_t)((c & 1) * BSH * 2);

#pragma unroll
        for (int ks = 0; ks < 4; ks++) {
            const uint32_t kso = (uint32_t)(ks * 32);
            uint32_t afr[2][4], afi[2][4];
            ldsm4(afr[0], aR0 + bufA + kso);
            ldsm4(afr[1], aR0 + bufA + kso + 2304);
            ldsm4(afi[0], aI0 + bufA + kso);
            ldsm4(afi[1], aI0 + bufA + kso + 2304);
#pragma unroll
            for (int ni = 0; ni < 4; ni++) {
                uint32_t bt[4], bfx[2];
                ldsm4(bt, bB0 + bufB + kso + (uint32_t)(ni * 1152));
                bfx[0] = bt[2] ^ 0x80008000u;
                bfx[1] = bt[3] ^ 0x80008000u;
#pragma unroll
                for (int mi = 0; mi < 2; mi++) {
                    mma16(cr[mi][ni], afr[mi], bt);
                    mma16(cr[mi][ni], afi[mi], CONJ ? (bt + 2) : bfx);
                    mma16(ci[mi][ni], afi[mi], bt);
                    mma16(ci[mi][ni], afr[mi], CONJ ? bfx : (bt + 2));
                }
            }
        }
        __syncthreads();
    }

    if (EXP_C) {
#pragma unroll
        for (int mi = 0; mi < 2; mi++)
#pragma unroll
            for (int ni = 0; ni < 4; ni++)
#pragma unroll
                for (int r = 0; r < 4; r++) {
                    cr[mi][ni][r] = __expf(cr[mi][ni][r] * alpha);
                    ci[mi][ni][r] = __expf(ci[mi][ni][r] * alpha);
                }
#pragma unroll
        for (int comp = 0; comp < 2; comp++) {
            float (*acc)[4][4] = comp ? ci : cr;
#pragma unroll
            for (int mi = 0; mi < 2; mi++) {
                float s0 = 0.f, s1 = 0.f;
#pragma unroll
                for (int ni = 0; ni < 4; ni++) {
                    s0 += acc[mi][ni][0] + acc[mi][ni][1];
                    s1 += acc[mi][ni][2] + acc[mi][ni][3];
                }
                s0 += __shfl_xor_sync(0xffffffffu, s0, 1);
                s0 += __shfl_xor_sync(0xffffffffu, s0, 2);
                s1 += __shfl_xor_sync(0xffffffffu, s1, 1);
                s1 += __shfl_xor_sync(0xffffffffu, s1, 2);
                if (quad == 0) {
                    int row = m0 + wm * 32 + mi * 16 + grp;
                    size_t base = ((size_t)(comp * BH_ + bz) * T_);
                    int slot = blockIdx.x * 2 + wn;
                    psum[(base + row) * 32 + slot] = s0;
                    psum[(base + row + 8) * 32 + slot] = s1;
                }
            }
        }
    }

    // Epilogue
#pragma unroll
    for (int mi = 0; mi < 2; mi++) {
#pragma unroll
        for (int ni = 0; ni < 4; ni++) {
            int m = m0 + wm * 32 + mi * 16 + grp;
            int n = n0 + wn * 32 + ni * 8 + quad * 2;
            float vr0, vr1, vr2, vr3, vi0, vi1, vi2, vi3;
            if (EXP_C) {
                vr0 = cr[mi][ni][0]; vr1 = cr[mi][ni][1];
                vr2 = cr[mi][ni][2]; vr3 = cr[mi][ni][3];
                vi0 = ci[mi][ni][0]; vi1 = ci[mi][ni][1];
                vi2 = ci[mi][ni][2]; vi3 = ci[mi][ni][3];
            } else {
                float br0 = 0.f, br1 = 0.f, bi0 = 0.f, bi1 = 0.f;
                if (biasr) {
                    br0 = biasr[n]; br1 = biasr[n + 1];
                    bi0 = biasi[n]; bi1 = biasi[n + 1];
                }
                vr0 = cr[mi][ni][0] * alpha + br0;
                vr1 = cr[mi][ni][1] * alpha + br1;
                vr2 = cr[mi][ni][2] * alpha + br0;
                vr3 = cr[mi][ni][3] * alpha + br1;
                vi0 = ci[mi][ni][0] * alpha + bi0;
                vi1 = ci[mi][ni][1] * alpha + bi1;
                vi2 = ci[mi][ni][2] * alpha + bi0;
                vi3 = ci[mi][ni][3] * alpha + bi1;
            }
            if (OUT_HALF) {
                __half* CrB = (__half*)Crv + (size_t)zb * sC1 + (size_t)zh * sC2;
                __half* CiB = (__half*)Civ + (size_t)zb * sC1 + (size_t)zh * sC2;
                *(__half2*)(CrB + (size_t)m * ldc + n) = __floats2half2_rn(vr0, vr1);
                *(__half2*)(CrB + (size_t)(m + 8) * ldc + n) = __floats2half2_rn(vr2, vr3);
                *(__half2*)(CiB + (size_t)m * ldc + n) = __floats2half2_rn(vi0, vi1);
                *(__half2*)(CiB + (size_t)(m + 8) * ldc + n) = __floats2half2_rn(vi2, vi3);
            } else {
                float* CrB = (float*)Crv + (size_t)zb * sC1 + (size_t)zh * sC2;
                float* CiB = (float*)Civ + (size_t)zb * sC1 + (size_t)zh * sC2;
                float2 v;
                v.x = vr0; v.y = vr1;
                *(float2*)(CrB + (size_t)m * ldc + n) = v;
                v.x = vr2; v.y = vr3;
                *(float2*)(CrB + (size_t)(m + 8) * ldc + n) = v;
                v.x = vi0; v.y = vi1;
                *(float2*)(CiB + (size_t)m * ldc + n) = v;
                v.x = vi2; v.y = vi3;
                *(float2*)(CiB + (size_t)(m + 8) * ldc + n) = v;
            }
        }
    }
}

// ---------------------------------------------------------------------------
// avg kernel (side stream): computes its own inv8 from psum, batches all 8
// head loads for MLP, streams the head-average. Depends only on e/psum.
// ---------------------------------------------------------------------------
__global__ __launch_bounds__(256) void avg_kernel(float* __restrict__ out)
{
    const int t = blockIdx.x;
    const int b = blockIdx.y;
    const int comp = blockIdx.z;
    const __half* buf = comp ? g_aw_i : g_aw_r;

    const int tid = threadIdx.x;
    __shared__ float inv8[H_];
    if (tid < H_) {
        size_t row = ((size_t)comp * BH_ + b * H_ + tid) * T_ + t;
        const float4* p = (const float4*)(g_psum + row * 32);
        float s = 0.f;
#pragma unroll
        for (int j = 0; j < 8; j++) {
            float4 v = p[j];
            s += (v.x + v.y) + (v.z + v.w);
        }
        inv8[tid] = 1.0f / s;
    }

    __half2 e[H_][2];
#pragma unroll
    for (int h = 0; h < H_; h++) {
        const __half2* p = (const __half2*)(buf +
            ((size_t)(b * H_ + h) * T_ + t) * T_ + (tid << 2));
        e[h][0] = p[0];
        e[h][1] = p[1];
    }
    __syncthreads();

    float4 acc = {0.f, 0.f, 0.f, 0.f};
#pragma unroll
    for (int h = 0; h < H_; h++) {
        float2 e0 = __half22float2(e[h][0]);
        float2 e1 = __half22float2(e[h][1]);
        const float iv = inv8[h];
        acc.x += e0.x * iv; acc.y += e0.y * iv;
        acc.z += e1.x * iv; acc.w += e1.y * iv;
    }
    const float inv8f = 1.0f / (float)H_;
    acc.x *= inv8f; acc.y *= inv8f; acc.z *= inv8f; acc.w *= inv8f;
    size_t o = OUT_OFF2 + (size_t)comp * BTT_ + ((size_t)b * T_ + t) * T_ + (tid << 2);
    *(float4*)&out[o] = acc;
}

// ---------------------------------------------------------------------------
// PV fp16: 4 accumulator groups, 3-stage pipeline. Row inverses computed
// in the PROLOGUE from g_psum (same summation order as the old inv_kernel,
// bit-identical) — no separate inv kernel, no dependency for avg.
// ---------------------------------------------------------------------------
__global__ __launch_bounds__(256, 2)
void pv_kernel()
{
    extern __shared__ __half smh[];
    constexpr int ASH = 64 * 72;
    constexpr int BSH = 64 * 72;
    __half* AsR = smh;
    __half* AsI = smh + 3 * ASH;
    __half* BsR = smh + 6 * ASH;
    __half* BsI = smh + 6 * ASH + 3 * BSH;

    __shared__ float invS[128];   // [comp 0/1][64 local m-rows]

    const int tid  = threadIdx.x;
    const int lane = tid & 31;
    const int warp = tid >> 5;
    const int wm   = warp & 3;
    const int wn   = warp >> 2;
    const int grp  = lane >> 2;
    const int quad = lane & 3;
    const int subm = lane >> 3;
    const int rin  = lane & 7;

    const int bh = blockIdx.y;
    const int b = bh >> 3, h = bh & 7;
    const int m0 = blockIdx.x << 6;

    const __half* ArB = g_aw_r + (size_t)bh * TT_;
    const __half* AiB = g_aw_i + (size_t)bh * TT_;

    const uint32_t sAsR = smem_u32(AsR);
    const uint32_t sAsI = smem_u32(AsI);
    const uint32_t sBsR = smem_u32(BsR);
    const uint32_t sBsI = smem_u32(BsI);

    const uint32_t aoff = (uint32_t)((wm * 16 + (subm & 1) * 8 + rin) * 144 +
                                     (subm >> 1) * 16);
    const uint32_t aR0 = sAsR + aoff;
    const uint32_t aI0 = sAsI + aoff;
    const uint32_t voff = (uint32_t)(((subm & 1) * 8 + rin) * 144 + wn * 64);
    const uint32_t vB0 = ((subm >> 1) ? sBsI : sBsR) + voff;

    float X[4][4], Y[4][4], Z[4][4], W[4][4];
#pragma unroll
    for (int ni = 0; ni < 4; ni++)
#pragma unroll
        for (int r = 0; r < 4; r++) {
            X[ni][r] = 0.f; Y[ni][r] = 0.f; Z[ni][r] = 0.f; W[ni][r] = 0.f;
        }

    auto load_chunk = [&](int c, int buf) {
        const int k0 = c << 6;
#pragma unroll
        for (int j = 0; j < 2; j++) {
            int idx = tid + j * 256;
            int row = idx >> 3;
            int c8  = (idx & 7) << 3;
            uint32_t so = (uint32_t)(buf * ASH * 2 + row * 144 + c8 * 2);
            cp16(sAsR + so, ArB + (size_t)(m0 + row) * T_ + k0 + c8);
            cp16(sAsI + so, AiB + (size_t)(m0 + row) * T_ + k0 + c8);
        }
#pragma unroll
        for (int j = 0; j < 2; j++) {
            int idx = tid + j * 256;
            int row = idx >> 3;
            int c8  = (idx & 7) << 3;
            uint32_t so = (uint32_t)(buf * BSH * 2 + row * 144 + c8 * 2);
            size_t voffg = ((size_t)(k0 + row) * B_ + b) * K3E + 2 * E_ + h * D_ + c8;
            cp16(sBsR + so, g_qkv_r + voffg);
            cp16(sBsI + so, g_qkv_i + voffg);
        }
        asm volatile("cp.async.commit_group;");
    };

    const int NC = T_ >> 6;
    load_chunk(0, 0);
    load_chunk(1, 1);

    // Prologue (overlaps the in-flight cp.async): row inverses from psum.
    // Same summation order as the old inv_kernel -> bit-identical values.
    if (tid < 128) {
        int comp = tid >> 6, ml = tid & 63;
        size_t row = ((size_t)(comp * BH_ + bh) * T_) + m0 + ml;
        const float4* p = (const float4*)(g_psum + row * 32);
        float s = 0.f;
#pragma unroll
        for (int j = 0; j < 8; j++) {
            float4 v = p[j];
            s += (v.x + v.y) + (v.z + v.w);
        }
        invS[tid] = 1.0f / s;
    }

    int sc = 0, sp = 2;
    for (int c = 0; c < NC; c++) {
        if (c + 1 < NC) asm volatile("cp.async.wait_group 1;");
        else            asm volatile("cp.async.wait_group 0;");
        __syncthreads();
        if (c + 2 < NC) {
            load_chunk(c + 2, sp);
            sp = (sp == 2) ? 0 : sp + 1;
        }

        const uint32_t bufA = (uint32_t)(sc * ASH * 2);
        const uint32_t bufB = (uint32_t)(sc * BSH * 2);
        sc = (sc == 2) ? 0 : sc + 1;

#pragma unroll
        for (int ks = 0; ks < 4; ks++) {
            const uint32_t kso = (uint32_t)(ks * 32);
            uint32_t aer[4], aei[4];
            ldsm4(aer, aR0 + bufA + kso);
            ldsm4(aei, aI0 + bufA + kso);
#pragma unroll
            for (int ni = 0; ni < 4; ni++) {
                uint32_t bt[4];
                ldsm4t(bt, vB0 + bufB + (uint32_t)(ks * 16 * 144) + (uint32_t)(ni * 16));
                mma16(X[ni], aer, bt);
                mma16(Y[ni], aei, bt + 2);
                mma16(Z[ni], aei, bt);
                mma16(W[ni], aer, bt + 2);
            }
        }
    }

    const int ml  = wm * 16 + grp;
    const int m   = m0 + ml;
    const float ir0 = invS[ml];
    const float ir1 = invS[ml + 8];
    const float ii0 = invS[64 + ml];
    const float ii1 = invS[64 + ml + 8];
#pragma unroll
    for (int ni = 0; ni < 4; ni++) {
        int n = wn * 32 + ni * 8 + quad * 2;
        size_t o0 = ((size_t)m * B_ + b) * E_ + h * D_ + n;
        size_t o1 = ((size_t)(m + 8) * B_ + b) * E_ + h * D_ + n;
        *(__half2*)(g_attn_r + o0) = __floats2half2_rn(
            ir0 * X[ni][0] + ii0 * Y[ni][0], ir0 * X[ni][1] + ii0 * Y[ni][1]);
        *(__half2*)(g_attn_r + o1) = __floats2half2_rn(
            ir1 * X[ni][2] + ii1 * Y[ni][2], ir1 * X[ni][3] + ii1 * Y[ni][3]);
        *(__half2*)(g_attn_i + o0) = __floats2half2_rn(
            ii0 * Z[ni][0] - ir0 * W[ni][0], ii0 * Z[ni][1] - ir0 * W[ni][1]);
        *(__half2*)(g_attn_i + o1) = __floats2half2_rn(
            ii1 * Z[ni][2] - ir1 * W[ni][2], ii1 * Z[ni][3] - ir1 * W[ni][3]);
    }
}

// ---------------------------------------------------------------------------
extern "C" void kernel_launch(void* const* d_in, const int* in_sizes, int n_in,
                              void* d_out, int out_size)
{
    const float* query_r = (const float*)d_in[0];
    const float* query_i = (const float*)d_in[1];
    const float* W_qkv_r = (const float*)d_in[2];
    const float* W_qkv_i = (const float*)d_in[3];
    const float* b_qkv_r = (const float*)d_in[4];
    const float* b_qkv_i = (const float*)d_in[5];
    const float* W_out_r = (const float*)d_in[6];
    const float* W_out_i = (const float*)d_in[7];
    const float* b_out_r = (const float*)d_in[8];
    const float* b_out_i = (const float*)d_in[9];
    float* out = (float*)d_out;

    __half *gqkvr, *gqkvi, *gawr, *gawi, *gatr, *gati;
    __half *gqtr, *gqti, *gwqr, *gwqi, *gwor, *gwoi;
    float *gpsum;
    cudaGetSymbolAddress((void**)&gqkvr, g_qkv_r);
    cudaGetSymbolAddress((void**)&gqkvi, g_qkv_i);
    cudaGetSymbolAddress((void**)&gawr, g_aw_r);
    cudaGetSymbolAddress((void**)&gawi, g_aw_i);
    cudaGetSymbolAddress((void**)&gatr, g_attn_r);
    cudaGetSymbolAddress((void**)&gati, g_attn_i);
    cudaGetSymbolAddress((void**)&gpsum, g_psum);
    cudaGetSymbolAddress((void**)&gqtr, g_qt_r);
    cudaGetSymbolAddress((void**)&gqti, g_qt_i);
    cudaGetSymbolAddress((void**)&gwqr, g_wqkv_r);
    cudaGetSymbolAddress((void**)&gwqi, g_wqkv_i);
    cudaGetSymbolAddress((void**)&gwor, g_wout_r);
    cudaGetSymbolAddress((void**)&gwoi, g_wout_i);

    // Side stream + events for avg overlap (host-side resources only).
    static cudaStream_t s2 = nullptr;
    static cudaEvent_t evFork = nullptr, evJoin = nullptr;
    if (s2 == nullptr) {
        cudaStreamCreateWithFlags(&s2, cudaStreamNonBlocking);
        cudaEventCreateWithFlags(&evFork, cudaEventDisableTiming);
        cudaEventCreateWithFlags(&evJoin, cudaEventDisableTiming);
    }

    const int SMEM_NK = (4 * 128 * 72 + 4 * 64 * 72) * 2;   // 110592 B
    const int SMEM_PV = (6 * 64 * 72 + 6 * 64 * 72) * 2;    // 110592 B

    cudaFuncSetAttribute((const void*)cmma_kernel<false, false, true>,
                         cudaFuncAttributeMaxDynamicSharedMemorySize, SMEM_NK);
    cudaFuncSetAttribute((const void*)cmma_kernel<true, true, true>,
                         cudaFuncAttributeMaxDynamicSharedMemorySize, SMEM_NK);
    cudaFuncSetAttribute((const void*)cmma_kernel<false, false, false>,
                         cudaFuncAttributeMaxDynamicSharedMemorySize, SMEM_NK);
    cudaFuncSetAttribute((const void*)pv_kernel,
                         cudaFuncAttributeMaxDynamicSharedMemorySize, SMEM_PV);

    dim3 blk(256);

    // 0) Convert all GEMM inputs to fp16
    cvt_all_kernel<<<(N4_TOTAL + 255) / 256, blk>>>(
        query_r, query_i, W_qkv_r, W_qkv_i, W_out_r, W_out_i,
        gqtr, gqti, gwqr, gwqi, gwor, gwoi);

    // 1) QKV complex linear (half outputs)
    cmma_kernel<false, false, true>
        <<<dim3(K3E / 64, M_ / 128, 1), blk, SMEM_NK>>>(
        gqtr, gqti, E_, 0, 0,
        gwqr, gwqi, E_, 0, 0,
        gqkvr, gqkvi, K3E, 0, 0,
        b_qkv_r, b_qkv_i, nullptr, 1.0f, E_);

    // 2) Scores -> e = exp(SCALE*logits) (half) + per-row psum
    cmma_kernel<true, true, true>
        <<<dim3(T_ / 64, T_ / 128, BH_), blk, SMEM_NK>>>(
        gqkvr, gqkvi, (long)B_ * K3E, K3E, D_,
        gqkvr + E_, gqkvi + E_, (long)B_ * K3E, K3E, D_,
        gawr, gawi, T_, (long)8 * TT_, (long)TT_,
        nullptr, nullptr, gpsum, SCALE_, D_);

    // ---- fork: avg (DRAM-bound) on s2, concurrent with PV + out ----
    cudaEventRecord(evFork, 0);
    cudaStreamWaitEvent(s2, evFork, 0);
    avg_kernel<<<dim3(T_, B_, 2), blk, 0, s2>>>(out);
    cudaEventRecord(evJoin, s2);

    // 3) PV (computes its own row inverses in-prologue)
    pv_kernel<<<dim3(T_ / 64, BH_), blk, SMEM_PV>>>();

    // 4) Output complex linear -> d_out head (float)
    cmma_kernel<false, false, false>
        <<<dim3(E_ / 64, M_ / 128, 1), blk, SMEM_NK>>>(
        gatr, gati, E_, 0, 0,
        gwor, gwoi, E_, 0, 0,
        out, out + (size_t)M_ * E_, E_, 0, 0,
        b_out_r, b_out_i, nullptr, 1.0f, E_);

    // ---- join ----
    cudaStreamWaitEvent(0, evJoin, 0);
}